// round 15
// baseline (speedup 1.0000x reference)
#include <cuda_runtime.h>
#include <cuda_fp16.h>
#include <cstdint>

#define SLEN  2048
#define DDIM  1024
#define NHEAD 16
#define HDIM  64
#define MAXB  2

using u32 = unsigned int;

// ---------------- scratch (device globals) ------------------------------------
__device__ __half g_wt [4L * DDIM * DDIM];                 // W{q,k,v,o}^T [n][k] fp16
__device__ float  g_b3 [3 * DDIM];                         // packed bq,bk,bv
__device__ __half g_xh [(long)MAXB * SLEN * DDIM];         // x in fp16
__device__ __half g_qk [2L * MAXB * SLEN * DDIM];          // Q (pre-scaled) then K
__device__ __half g_vt [(long)MAXB * NHEAD * HDIM * SLEN]; // V^T [b][h][d][s]
__device__ __half g_E  [(long)MAXB * NHEAD * SLEN * SLEN]; // exp(scores), PERMUTED layout
__device__ __half g_ctx[(long)MAXB * SLEN * DDIM];
__device__ float  g_rs [MAXB * NHEAD * SLEN];              // 1/rowsum

#define QSCALE 0.1803368801111204f   // log2(e) / 8

// Permuted E layout: region r = ((bh*64 + rowblk)*16 + kt)*2 + wn, 1024 u32 each.
//   within region: u32 idx = ch*32 + gid*4 + tg, ch = (((mi*2+hh)*4+nj)*2+p8)
//   row  = rowblk*32 + mi*16 + p8*8 + gid
//   cols = kt*128 + wn*64 + hh*32 + nj*8 + 2*tg + {0,1}

// ---------------- helpers ------------------------------------------------------
__device__ __forceinline__ u32 pkh2(float a, float b) {
    __half2 h = __floats2half2_rn(a, b);
    return *(u32*)&h;
}

__device__ __forceinline__ u32 ex2h2(u32 x) {
    u32 r;
    asm("ex2.approx.f16x2 %0, %1;" : "=r"(r) : "r"(x));
    return r;
}

__device__ __forceinline__ void hmma(float* c, const u32* a, const u32* b) {
    asm volatile(
        "mma.sync.aligned.m16n8k16.row.col.f32.f16.f16.f32 "
        "{%0,%1,%2,%3},{%4,%5,%6,%7},{%8,%9},{%0,%1,%2,%3};"
        : "+f"(c[0]), "+f"(c[1]), "+f"(c[2]), "+f"(c[3])
        : "r"(a[0]), "r"(a[1]), "r"(a[2]), "r"(a[3]), "r"(b[0]), "r"(b[1]));
}

__device__ __forceinline__ void ldsm4(u32& r0, u32& r1, u32& r2, u32& r3, u32 saddr) {
    asm volatile("ldmatrix.sync.aligned.m8n8.x4.shared.b16 {%0,%1,%2,%3}, [%4];"
                 : "=r"(r0), "=r"(r1), "=r"(r2), "=r"(r3) : "r"(saddr));
}

__device__ __forceinline__ void cpa16(u32 dst, const void* src) {
    asm volatile("cp.async.cg.shared.global [%0], [%1], 16;" :: "r"(dst), "l"(src));
}
__device__ __forceinline__ void cpa_commit() {
    asm volatile("cp.async.commit_group;" ::: "memory");
}
__device__ __forceinline__ void cpa_wait1() {
    asm volatile("cp.async.wait_group 1;" ::: "memory");
}

// ---------------- GEMM core: BM=128,BN=128,BK=64, 8 warps (WGM=2,WGN=4) ---------
__device__ __forceinline__ void gemm_core_128(
    const __half* __restrict__ Agp, const __half* __restrict__ Bgp,
    int K, int lda, int ldb, u32 sbase, float (*acc)[4])
{
    constexpr int BK = 64, BKP = 72;
    constexpr u32 TSTG = 128 * BKP * 2;
    constexpr u32 STG = 2 * TSTG;

    const int tid = threadIdx.x;
    const int w = tid >> 5, lane = tid & 31;
    const int wm = w & 1, wn = w >> 1;
    const int q8 = lane >> 3, r8 = lane & 7;
    const int rowA = wm * 64 + (q8 & 1) * 8 + r8, colA = (q8 >> 1) * 8;
    const int rowB = wn * 32 + (q8 >> 1) * 8 + r8, colB = (q8 & 1) * 8;

#pragma unroll
    for (int i = 0; i < 16; ++i)
#pragma unroll
        for (int r = 0; r < 4; ++r) acc[i][r] = 0.f;

    auto issue = [&](int stage, int kb) {
        const u32 ab = sbase + stage * STG;
#pragma unroll
        for (int i = 0; i < 4; ++i) {
            int c = tid + i * 256; int row = c >> 3, ku = c & 7;
            cpa16(ab + (u32)(row * BKP + ku * 8) * 2, Agp + (long)row * lda + kb + ku * 8);
        }
        const u32 bb = sbase + stage * STG + TSTG;
#pragma unroll
        for (int i = 0; i < 4; ++i) {
            int c = tid + i * 256; int row = c >> 3, ku = c & 7;
            cpa16(bb + (u32)(row * BKP + ku * 8) * 2, Bgp + (long)row * ldb + kb + ku * 8);
        }
        cpa_commit();
    };

    const int KT = K / BK;
    issue(0, 0);
    issue(1, BK);

    for (int kt = 0; kt < KT; ++kt) {
        cpa_wait1();
        __syncthreads();
        if (kt + 2 < KT) issue((kt + 2) % 3, (kt + 2) * BK);
        else cpa_commit();

        const int stage = kt % 3;
        const u32 ab = sbase + stage * STG;
        const u32 bb = ab + TSTG;
#pragma unroll
        for (int ks = 0; ks < 4; ++ks) {
            const int kk = ks * 16;
            u32 a[4][4], b[4][2];
#pragma unroll
            for (int mi = 0; mi < 4; ++mi)
                ldsm4(a[mi][0], a[mi][1], a[mi][2], a[mi][3],
                      ab + (u32)((rowA + mi * 16) * BKP + kk + colA) * 2);
#pragma unroll
            for (int p = 0; p < 2; ++p)
                ldsm4(b[2 * p][0], b[2 * p][1], b[2 * p + 1][0], b[2 * p + 1][1],
                      bb + (u32)((rowB + p * 16) * BKP + kk + colB) * 2);
#pragma unroll
            for (int mi = 0; mi < 4; ++mi)
#pragma unroll
                for (int nj = 0; nj < 4; ++nj)
                    hmma(acc[mi * 4 + nj], a[mi], b[nj]);
        }
    }
}

// ---------------- QKV projection (z selects Q/K/V; Q pre-scaled by QSCALE) ------
__global__ void __launch_bounds__(256, 2)
qkv_proj(const __half* __restrict__ xh, const __half* __restrict__ wt,
         const float* __restrict__ b3, __half* __restrict__ qk,
         __half* __restrict__ vt, long QKoff)
{
    extern __shared__ __align__(16) __half smem[];
    const u32 sbase = (u32)__cvta_generic_to_shared(smem);
    const int z = blockIdx.z;
    const int m0 = blockIdx.y * 128, n0 = blockIdx.x * 128;

    const __half* Agp = xh + (long)m0 * DDIM;
    const __half* Bgp = wt + (long)z * DDIM * DDIM + (long)n0 * DDIM;
    const float* bias = b3 + z * DDIM;

    float acc[16][4];
    gemm_core_128(Agp, Bgp, DDIM, DDIM, DDIM, sbase, acc);

    const int tid = threadIdx.x;
    const int w = tid >> 5, lane = tid & 31;
    const int wm = w & 1, wn = w >> 1;
    const int gid = lane >> 2, tg = lane & 3;

    if (z < 2) {
        const float sc = (z == 0) ? QSCALE : 1.f;
        __half* Ch = qk + z * QKoff;
#pragma unroll
        for (int mi = 0; mi < 4; ++mi) {
            int r = m0 + wm * 64 + mi * 16 + gid;
#pragma unroll
            for (int nj = 0; nj < 4; ++nj) {
                int n = n0 + wn * 32 + nj * 8 + 2 * tg;
                float b0 = bias[n], b1 = bias[n + 1];
                float* c = acc[mi * 4 + nj];
                *(u32*)&Ch[(long)r * DDIM + n]       = pkh2((c[0] + b0) * sc, (c[1] + b1) * sc);
                *(u32*)&Ch[(long)(r + 8) * DDIM + n] = pkh2((c[2] + b0) * sc, (c[3] + b1) * sc);
            }
        }
    } else {
#pragma unroll
        for (int mi = 0; mi < 4; ++mi) {
            int r = m0 + wm * 64 + mi * 16 + gid;
#pragma unroll
            for (int nj = 0; nj < 4; ++nj) {
                int n = n0 + wn * 32 + nj * 8 + 2 * tg;
                float b0 = bias[n], b1 = bias[n + 1];
                float* c = acc[mi * 4 + nj];
                int bb0 = r >> 11, s0 = r & 2047;
                int bb1 = (r + 8) >> 11, s1 = (r + 8) & 2047;
                long base0 = ((long)(bb0 * NHEAD) * HDIM) * SLEN;
                long base1 = ((long)(bb1 * NHEAD) * HDIM) * SLEN;
                vt[base0 + (long)n * SLEN + s0]       = __float2half(c[0] + b0);
                vt[base0 + (long)(n + 1) * SLEN + s0] = __float2half(c[1] + b1);
                vt[base1 + (long)n * SLEN + s1]       = __float2half(c[2] + b0);
                vt[base1 + (long)(n + 1) * SLEN + s1] = __float2half(c[3] + b1);
            }
        }
    }
}

// ---------------- merged out-projection + region-major attn_mean -----------------
__global__ void __launch_bounds__(256, 2)
outmerge(const __half* __restrict__ ctx, const __half* __restrict__ wo,
         const float* __restrict__ bo, float* __restrict__ out,
         const __half* __restrict__ E, const float* __restrict__ rs,
         float* __restrict__ attn)
{
    const int bid = blockIdx.x;
    const int tid = threadIdx.x;

    if (bid < 256) {
        extern __shared__ __align__(16) __half smem[];
        const u32 sbase = (u32)__cvta_generic_to_shared(smem);
        const int m0 = (bid >> 3) * 128, n0 = (bid & 7) * 128;
        const __half* Agp = ctx + (long)m0 * DDIM;
        const __half* Bgp = wo + (long)n0 * DDIM;

        float acc[16][4];
        gemm_core_128(Agp, Bgp, DDIM, DDIM, DDIM, sbase, acc);

        const int w = tid >> 5, lane = tid & 31;
        const int wm = w & 1, wn = w >> 1;
        const int gid = lane >> 2, tg = lane & 3;
#pragma unroll
        for (int mi = 0; mi < 4; ++mi) {
            int r = m0 + wm * 64 + mi * 16 + gid;
#pragma unroll
            for (int nj = 0; nj < 4; ++nj) {
                int n = n0 + wn * 32 + nj * 8 + 2 * tg;
                float b0 = bo[n], b1 = bo[n + 1];
                float* c = acc[mi * 4 + nj];
                *(float2*)&out[(long)r * DDIM + n]       = make_float2(c[0] + b0, c[1] + b1);
                *(float2*)&out[(long)(r + 8) * DDIM + n] = make_float2(c[2] + b0, c[3] + b1);
            }
        }
    } else {
        const int id = bid - 256;
        const int kt = id & 15;
        const int rowblk = (id >> 4) & 63;
        const int b = id >> 10;

        __shared__ float siz2[NHEAD][32];
        for (int i = tid; i < NHEAD * 32; i += 256) {
            int hh2 = i >> 5, r = i & 31;
            siz2[hh2][r] = rs[(long)(b * NHEAD + hh2) * SLEN + rowblk * 32 + r];
        }
        __syncthreads();

        const int ch = tid >> 3, gid = tid & 7;
        const int mi = (ch >> 4) & 1, hhb = (ch >> 3) & 1, nj = (ch >> 1) & 3, p8 = ch & 1;
        const int row = mi * 16 + p8 * 8 + gid;
        const int colb = hhb * 32 + nj * 8;

        const u32* Eu = (const u32*)E;
        const long regbase0 = ((((long)(b * NHEAD) * 64 + rowblk) * 16 + kt) * 2);

        float a0[8] = {0,0,0,0,0,0,0,0};
        float a1[8] = {0,0,0,0,0,0,0,0};
#pragma unroll
        for (int h = 0; h < NHEAD; ++h) {
            float z = siz2[h][row];
            const u32* rg = Eu + (regbase0 + (long)h * (64 * 16 * 2)) * 1024 + tid * 4;
            uint4 e0 = *(const uint4*)rg;
            uint4 e1 = *(const uint4*)(rg + 1024);
            float2 f;
            f = __half22float2(*(__half2*)&e0.x); a0[0] += f.x * z; a0[1] += f.y * z;
            f = __half22float2(*(__half2*)&e0.y); a0[2] += f.x * z; a0[3] += f.y * z;
            f = __half22float2(*(__half2*)&e0.z); a0[4] += f.x * z; a0[5] += f.y * z;
            f = __half22float2(*(__half2*)&e0.w); a0[6] += f.x * z; a0[7] += f.y * z;
            f = __half22float2(*(__half2*)&e1.x); a1[0] += f.x * z; a1[1] += f.y * z;
            f = __half22float2(*(__half2*)&e1.y); a1[2] += f.x * z; a1[3] += f.y * z;
            f = __half22float2(*(__half2*)&e1.z); a1[4] += f.x * z; a1[5] += f.y * z;
            f = __half22float2(*(__half2*)&e1.w); a1[6] += f.x * z; a1[7] += f.y * z;
        }
        const float sc = 1.f / (float)NHEAD;
        float* o = attn + ((long)b * SLEN + rowblk * 32 + row) * SLEN + kt * 128 + colb;
        *(float4*)&o[0]  = make_float4(a0[0] * sc, a0[1] * sc, a0[2] * sc, a0[3] * sc);
        *(float4*)&o[4]  = make_float4(a0[4] * sc, a0[5] * sc, a0[6] * sc, a0[7] * sc);
        *(float4*)&o[64] = make_float4(a1[0] * sc, a1[1] * sc, a1[2] * sc, a1[3] * sc);
        *(float4*)&o[68] = make_float4(a1[4] * sc, a1[5] * sc, a1[6] * sc, a1[7] * sc);
    }
}

// ---------------- fused attention v7: Z on fma pipe, permuted E stores -----------
__global__ void __launch_bounds__(128, 2)
fused_attn(const __half* __restrict__ Q, const __half* __restrict__ Kg,
           const __half* __restrict__ Vt, __half* __restrict__ E,
           __half* __restrict__ ctx, float* __restrict__ rs)
{
    constexpr int QP = 72;
    constexpr int VP = 136;
    constexpr int KTILE = 128 * QP;
    constexpr int VTILE = 64 * VP;
    constexpr int STAGE = KTILE + VTILE;
    constexpr int NC = SLEN / 128;

    const int tid = threadIdx.x;
    const int m0 = blockIdx.x * 64;
    const int bh = blockIdx.y;
    const int b = bh / NHEAD, h = bh % NHEAD;

    const __half* Qg = Q  + ((long)b * SLEN + m0) * DDIM + h * HDIM;
    const __half* Kb = Kg + ((long)b * SLEN) * DDIM + h * HDIM;
    const __half* Vg = Vt + (long)bh * HDIM * SLEN;

    const int w = tid >> 5, lane = tid & 31;
    const int gid = lane >> 2, tg = lane & 3;
    const int wm = w & 1, wn = w >> 1;
    const int q8 = lane >> 3, r8 = lane & 7;
    const int rowA = wm * 32 + (q8 & 1) * 8 + r8, colA = (q8 >> 1) * 8;
    const int rowB = wn * 64 + (q8 >> 1) * 8 + r8, colB = (q8 & 1) * 8;
    const int rowV = (q8 >> 1) * 8 + r8,            colV = (q8 & 1) * 8;

    u32* Eu = (u32*)E;
    const long rb16 = ((long)bh * 64 + blockIdx.x * 2 + wm) * 16;

    extern __shared__ __align__(16) __half smem[];
    const u32 sbase = (u32)__cvta_generic_to_shared(smem);
    auto kb = [&](int s) { return sbase + (u32)(s * STAGE) * 2; };
    auto vb = [&](int s) { return sbase + (u32)(s * STAGE + KTILE) * 2; };
    const u32 qb = kb(2);

    __shared__ float zs[2][32][2];
    __shared__ float siz[64];

    auto load_q = [&]() {
#pragma unroll
        for (int i = 0; i < 4; ++i) {
            int c = tid + i * 128; int row = c >> 3, cq = c & 7;
            cpa16(qb + (row * QP + cq * 8) * 2, Qg + (long)row * DDIM + cq * 8);
        }
    };
    auto issue = [&](int chunk) {
        const int stage = chunk % 3;
        const __half* Kp = Kb + (long)(chunk * 128) * DDIM;
        const u32 kbs = kb(stage);
#pragma unroll
        for (int i = 0; i < 8; ++i) {
            int c = tid + i * 128; int row = c >> 3, cq = c & 7;
            cpa16(kbs + (row * QP + cq * 8) * 2, Kp + (long)row * DDIM + cq * 8);
        }
        const __half* Vp = Vg + chunk * 128;
        const u32 vbs = vb(stage);
#pragma unroll
        for (int i = 0; i < 8; ++i) {
            int c = tid + i * 128; int row = c >> 4, cv = c & 15;
            cpa16(vbs + (row * VP + cv * 8) * 2, Vp + (long)row * SLEN + cv * 8);
        }
        cpa_commit();
    };

    float cU[2][8][4];
#pragma unroll
    for (int mi = 0; mi < 2; ++mi)
#pragma unroll
        for (int dj = 0; dj < 8; ++dj)
#pragma unroll
            for (int r = 0; r < 4; ++r) cU[mi][dj][r] = 0.f;
    float zacc[2][2] = {{0.f, 0.f}, {0.f, 0.f}};   // Z on scalar pipe

    u32 qf[2][4][4];

    load_q();
    issue(0);
    issue(1);

    for (int kt = 0; kt < NC; ++kt) {
        cpa_wait1();
        __syncthreads();

        if (kt == 0) {
#pragma unroll
            for (int mi = 0; mi < 2; ++mi)
#pragma unroll
                for (int kf = 0; kf < 4; ++kf)
                    ldsm4(qf[mi][kf][0], qf[mi][kf][1], qf[mi][kf][2], qf[mi][kf][3],
                          qb + ((rowA + mi * 16) * QP + kf * 16 + colA) * 2);
            __syncthreads();
        }

        if (kt + 2 < NC) issue(kt + 2);
        else cpa_commit();

        const int stage = kt % 3;
        const u32 kbs = kb(stage), vbs = vb(stage);
        u32* Ew = Eu + ((rb16 + kt) * 2 + wn) * 1024 + lane;

#pragma unroll
        for (int hh = 0; hh < 2; ++hh) {
            float cS[2][4][4];
#pragma unroll
            for (int mi = 0; mi < 2; ++mi)
#pragma unroll
                for (int nj = 0; nj < 4; ++nj)
#pragma unroll
                    for (int r = 0; r < 4; ++r) cS[mi][nj][r] = 0.f;

#pragma unroll
            for (int kf = 0; kf < 4; ++kf) {
                const int kk = kf * 16;
                u32 bfr[4][2];
#pragma unroll
                for (int p = 0; p < 2; ++p) {
                    const int pg = 2 * hh + p;
                    ldsm4(bfr[2 * p][0], bfr[2 * p][1], bfr[2 * p + 1][0], bfr[2 * p + 1][1],
                          kbs + ((rowB + pg * 16) * QP + kk + colB) * 2);
                }
#pragma unroll
                for (int mi = 0; mi < 2; ++mi)
#pragma unroll
                    for (int nj = 0; nj < 4; ++nj)
                        hmma(cS[mi][nj], qf[mi][kf], bfr[nj]);
            }

            // E = 2^S' in fp16; Z accumulated in f32 on the (idle) fma pipe
            u32 eh[2][4][2];
#pragma unroll
            for (int mi = 0; mi < 2; ++mi)
#pragma unroll
                for (int nj = 0; nj < 4; ++nj) {
                    eh[mi][nj][0] = ex2h2(pkh2(cS[mi][nj][0], cS[mi][nj][1]));
                    eh[mi][nj][1] = ex2h2(pkh2(cS[mi][nj][2], cS[mi][nj][3]));
                    float2 f0 = __half22float2(*(__half2*)&eh[mi][nj][0]);
                    float2 f1 = __half22float2(*(__half2*)&eh[mi][nj][1]);
                    zacc[mi][0] += f0.x + f0.y;
                    zacc[mi][1] += f1.x + f1.y;
                }

#pragma unroll
            for (int j = 0; j < 2; ++j) {
                const int kfu = 2 * hh + j;
                const int kk2 = kfu * 16;
                u32 a[2][4], bv[8][2];
#pragma unroll
                for (int mi = 0; mi < 2; ++mi) {
                    a[mi][0] = eh[mi][2 * j][0];
                    a[mi][1] = eh[mi][2 * j][1];
                    a[mi][2] = eh[mi][2 * j + 1][0];
                    a[mi][3] = eh[mi][2 * j + 1][1];
                }
#pragma unroll
                for (int p = 0; p < 4; ++p)
                    ldsm4(bv[2 * p][0], bv[2 * p][1], bv[2 * p + 1][0], bv[2 * p + 1][1],
                          vbs + ((rowV + p * 16) * VP + wn * 64 + kk2 + colV) * 2);
#pragma unroll
                for (int mi = 0; mi < 2; ++mi)
#pragma unroll
                    for (int dj = 0; dj < 8; ++dj)
                        hmma(cU[mi][dj], a[mi], bv[dj]);
            }

#pragma unroll
            for (int mi = 0; mi < 2; ++mi)
#pragma unroll
                for (int nj = 0; nj < 4; ++nj) {
                    const int ch = ((mi * 2 + hh) * 4 + nj) * 2;
                    Ew[(u32)(ch * 32)]       = eh[mi][nj][0];
                    Ew[(u32)((ch + 1) * 32)] = eh[mi][nj][1];
                }
        }
    }

    __syncthreads();

    // ---- Z reduce: over tg lanes (shfl), then across wn via smem --------------------
#pragma unroll
    for (int mi = 0; mi < 2; ++mi)
#pragma unroll
        for (int r = 0; r < 2; ++r) {
            float v = zacc[mi][r];
            v += __shfl_xor_sync(0xffffffffu, v, 1);
            v += __shfl_xor_sync(0xffffffffu, v, 2);
            zacc[mi][r] = v;
        }
    if (tg == 0) {
#pragma unroll
        for (int mi = 0; mi < 2; ++mi)
#pragma unroll
            for (int r = 0; r < 2; ++r)
                zs[wm][mi * 16 + r * 8 + gid][wn] = zacc[mi][r];
    }
    __syncthreads();
    if (tid < 64) {
        float inv = 1.f / (zs[tid >> 5][tid & 31][0] + zs[tid >> 5][tid & 31][1]);
        siz[tid] = inv;
        rs[(long)bh * SLEN + m0 + tid] = inv;
    }
    __syncthreads();

    // ---- cross-warp U reduce (2-way over wn) through smem ---------------------------
    float* Ured = (float*)smem;
    if (wn == 1) {
#pragma unroll
        for (int mi = 0; mi < 2; ++mi) {
            int r = wm * 32 + mi * 16 + gid;
#pragma unroll
            for (int dj = 0; dj < 8; ++dj) {
                int n = dj * 8 + 2 * tg;
                *(float2*)&Ured[r * 68 + n]       = make_float2(cU[mi][dj][0], cU[mi][dj][1]);
                *(float2*)&Ured[(r + 8) * 68 + n] = make_float2(cU[mi][dj][2], cU[mi][dj][3]);
            }
        }
    }
    __syncthreads();
    if (wn == 0) {
#pragma unroll
        for (int mi = 0; mi < 2; ++mi) {
            int r = wm * 32 + mi * 16 + gid;
            float iz0 = siz[r], iz1 = siz[r + 8];
            __half* C0 = ctx + ((long)b * SLEN + m0 + r) * DDIM + h * HDIM;
#pragma unroll
            for (int dj = 0; dj < 8; ++dj) {
                int n = dj * 8 + 2 * tg;
                float2 u0 = *(const float2*)&Ured[r * 68 + n];
                float2 u1 = *(const float2*)&Ured[(r + 8) * 68 + n];
                *(u32*)&C0[n] = pkh2((cU[mi][dj][0] + u0.x) * iz0,
                                     (cU[mi][dj][1] + u0.y) * iz0);
                *(u32*)&C0[8L * DDIM + n] = pkh2((cU[mi][dj][2] + u1.x) * iz1,
                                                 (cU[mi][dj][3] + u1.y) * iz1);
            }
        }
    }
}

// ---------------- prep kernels ----------------------------------------------------
__global__ void __launch_bounds__(256)
prep_w(const float* __restrict__ W0, const float* __restrict__ W1,
       const float* __restrict__ W2, const float* __restrict__ W3,
       __half* __restrict__ Wt)
{
    const int z = blockIdx.z;
    const float* W = (z == 0) ? W0 : (z == 1) ? W1 : (z == 2) ? W2 : W3;
    __half* T = Wt + (long)z * DDIM * DDIM;
    __shared__ float t[32][33];
    const int tx = threadIdx.x, ty = threadIdx.y;
    const int n0 = blockIdx.x * 32, k0 = blockIdx.y * 32;
#pragma unroll
    for (int i = 0; i < 4; ++i)
        t[tx][ty + 8 * i] = W[(long)(k0 + ty + 8 * i) * DDIM + n0 + tx];
    __syncthreads();
#pragma unroll
    for (int i = 0; i < 4; ++i)
        T[(long)(n0 + ty + 8 * i) * DDIM + k0 + tx] = __float2half(t[ty + 8 * i][tx]);
}

__global__ void __launch_bounds__(256)
prep_x(const float* __restrict__ x, __half* __restrict__ xh)
{
    long i = ((long)blockIdx.x * 256 + threadIdx.x) * 8;
    float4 f0 = *(const float4*)(x + i);
    float4 f1 = *(const float4*)(x + i + 4);
    uint4 u;
    u.x = pkh2(f0.x, f0.y); u.y = pkh2(f0.z, f0.w);
    u.z = pkh2(f1.x, f1.y); u.w = pkh2(f1.z, f1.w);
    *(uint4*)(xh + i) = u;
}

// ---------------- launch -----------------------------------------------------------
extern "C" void kernel_launch(void* const* d_in, const int* in_sizes, int n_in,
                              void* d_out, int out_size)
{
    const float* x  = (const float*)d_in[0];
    const float* Wq = (const float*)d_in[1];
    const float* bq = (const float*)d_in[2];
    const float* Wk = (const float*)d_in[3];
    const float* bk = (const float*)d_in[4];
    const float* Wv = (const float*)d_in[5];
    const float* bv = (const float*)d_in[6];
    const float* Wo = (const float*)d_in[7];
    const float* bo = (const float*)d_in[8];
    float* out = (float*)d_out;

    const int Bsz = in_sizes[0] / (SLEN * DDIM);   // = 2
    const int BS  = Bsz * SLEN;
    const long NB = (long)BS * DDIM;

    __half *wt, *xh, *qk, *vt, *E, *ctx;
    float *b3, *rs;
    cudaGetSymbolAddress((void**)&wt,  g_wt);
    cudaGetSymbolAddress((void**)&b3,  g_b3);
    cudaGetSymbolAddress((void**)&xh,  g_xh);
    cudaGetSymbolAddress((void**)&qk,  g_qk);
    cudaGetSymbolAddress((void**)&vt,  g_vt);
    cudaGetSymbolAddress((void**)&E,   g_E);
    cudaGetSymbolAddress((void**)&ctx, g_ctx);
    cudaGetSymbolAddress((void**)&rs,  g_rs);

    const int SM_P = 3 * 2 * 128 * 72 * 2;                 // 110592 (gemm core)
    const int SM_F = 3 * (128 * 72 + 64 * 136) * 2;        // 107520 (fused v7)
    cudaFuncSetAttribute(qkv_proj,   cudaFuncAttributeMaxDynamicSharedMemorySize, SM_P);
    cudaFuncSetAttribute(outmerge,   cudaFuncAttributeMaxDynamicSharedMemorySize, SM_P);
    cudaFuncSetAttribute(fused_attn, cudaFuncAttributeMaxDynamicSharedMemorySize, SM_F);

    cudaMemcpyAsync(b3,            bq, sizeof(float) * DDIM, cudaMemcpyDeviceToDevice);
    cudaMemcpyAsync(b3 + DDIM,     bk, sizeof(float) * DDIM, cudaMemcpyDeviceToDevice);
    cudaMemcpyAsync(b3 + 2 * DDIM, bv, sizeof(float) * DDIM, cudaMemcpyDeviceToDevice);

    prep_x<<<(unsigned)(NB / (256 * 8)), 256>>>(x, xh);
    prep_w<<<dim3(32, 32, 4), dim3(32, 8)>>>(Wq, Wk, Wv, Wo, wt);

    const long QKoff = (long)BS * DDIM;

    qkv_proj<<<dim3(8, BS / 128, 3), 256, SM_P>>>(xh, wt, b3, qk, vt, QKoff);

    fused_attn<<<dim3(SLEN / 64, Bsz * NHEAD), 128, SM_F>>>(
        qk, qk + QKoff, vt, E, ctx, rs);

    outmerge<<<256 + Bsz * 1024, 256, SM_P>>>(
        ctx, wt + 3L * DDIM * DDIM, bo, out, E, rs, out + NB);
}

// round 16
// speedup vs baseline: 1.0112x; 1.0112x over previous
#include <cuda_runtime.h>
#include <cuda_fp16.h>
#include <cstdint>

#define SLEN  2048
#define DDIM  1024
#define NHEAD 16
#define HDIM  64
#define MAXB  2

using u32 = unsigned int;

// ---------------- scratch (device globals) ------------------------------------
__device__ __half g_wt [4L * DDIM * DDIM];                 // W{q,k,v,o}^T [n][k] fp16
__device__ float  g_b3 [3 * DDIM];                         // packed bq,bk,bv
__device__ __half g_xh [(long)MAXB * SLEN * DDIM];         // x in fp16
__device__ __half g_qk [2L * MAXB * SLEN * DDIM];          // Q (pre-scaled) then K
__device__ __half g_vt [(long)MAXB * NHEAD * HDIM * SLEN]; // V^T [b][h][d][s]
__device__ __half g_E  [(long)MAXB * NHEAD * SLEN * SLEN]; // exp(scores), PERMUTED layout
__device__ __half g_ctx[(long)MAXB * SLEN * DDIM];
__device__ float  g_rs [MAXB * NHEAD * SLEN];              // 1/rowsum

#define QSCALE 0.1803368801111204f   // log2(e) / 8

// Permuted E layout: region r = ((bh*64 + rowblk)*16 + kt)*2 + wn, 1024 u32 each.
//   within region: u32 idx = ch*32 + gid*4 + tg, ch = (((mi*2+hh)*4+nj)*2+p8)
//   row  = rowblk*32 + mi*16 + p8*8 + gid
//   cols = kt*128 + wn*64 + hh*32 + nj*8 + 2*tg + {0,1}

// ---------------- helpers ------------------------------------------------------
__device__ __forceinline__ u32 pkh2(float a, float b) {
    __half2 h = __floats2half2_rn(a, b);
    return *(u32*)&h;
}

__device__ __forceinline__ u32 ex2h2(u32 x) {
    u32 r;
    asm("ex2.approx.f16x2 %0, %1;" : "=r"(r) : "r"(x));
    return r;
}

__device__ __forceinline__ void hmma(float* c, const u32* a, const u32* b) {
    asm volatile(
        "mma.sync.aligned.m16n8k16.row.col.f32.f16.f16.f32 "
        "{%0,%1,%2,%3},{%4,%5,%6,%7},{%8,%9},{%0,%1,%2,%3};"
        : "+f"(c[0]), "+f"(c[1]), "+f"(c[2]), "+f"(c[3])
        : "r"(a[0]), "r"(a[1]), "r"(a[2]), "r"(a[3]), "r"(b[0]), "r"(b[1]));
}

__device__ __forceinline__ void ldsm4(u32& r0, u32& r1, u32& r2, u32& r3, u32 saddr) {
    asm volatile("ldmatrix.sync.aligned.m8n8.x4.shared.b16 {%0,%1,%2,%3}, [%4];"
                 : "=r"(r0), "=r"(r1), "=r"(r2), "=r"(r3) : "r"(saddr));
}

__device__ __forceinline__ void ldsm2(u32& r0, u32& r1, u32 saddr) {
    asm volatile("ldmatrix.sync.aligned.m8n8.x2.shared.b16 {%0,%1}, [%2];"
                 : "=r"(r0), "=r"(r1) : "r"(saddr));
}

__device__ __forceinline__ void cpa16(u32 dst, const void* src) {
    asm volatile("cp.async.cg.shared.global [%0], [%1], 16;" :: "r"(dst), "l"(src));
}
__device__ __forceinline__ void cpa_commit() {
    asm volatile("cp.async.commit_group;" ::: "memory");
}
__device__ __forceinline__ void cpa_wait1() {
    asm volatile("cp.async.wait_group 1;" ::: "memory");
}

// ---------------- GEMM core: BM=128,BN=128,BK=64, 8 warps (WGM=2,WGN=4) ---------
__device__ __forceinline__ void gemm_core_128(
    const __half* __restrict__ Agp, const __half* __restrict__ Bgp,
    int K, int lda, int ldb, u32 sbase, float (*acc)[4])
{
    constexpr int BK = 64, BKP = 72;
    constexpr u32 TSTG = 128 * BKP * 2;
    constexpr u32 STG = 2 * TSTG;

    const int tid = threadIdx.x;
    const int w = tid >> 5, lane = tid & 31;
    const int wm = w & 1, wn = w >> 1;
    const int q8 = lane >> 3, r8 = lane & 7;
    const int rowA = wm * 64 + (q8 & 1) * 8 + r8, colA = (q8 >> 1) * 8;
    const int rowB = wn * 32 + (q8 >> 1) * 8 + r8, colB = (q8 & 1) * 8;

#pragma unroll
    for (int i = 0; i < 16; ++i)
#pragma unroll
        for (int r = 0; r < 4; ++r) acc[i][r] = 0.f;

    auto issue = [&](int stage, int kb) {
        const u32 ab = sbase + stage * STG;
#pragma unroll
        for (int i = 0; i < 4; ++i) {
            int c = tid + i * 256; int row = c >> 3, ku = c & 7;
            cpa16(ab + (u32)(row * BKP + ku * 8) * 2, Agp + (long)row * lda + kb + ku * 8);
        }
        const u32 bb = sbase + stage * STG + TSTG;
#pragma unroll
        for (int i = 0; i < 4; ++i) {
            int c = tid + i * 256; int row = c >> 3, ku = c & 7;
            cpa16(bb + (u32)(row * BKP + ku * 8) * 2, Bgp + (long)row * ldb + kb + ku * 8);
        }
        cpa_commit();
    };

    const int KT = K / BK;
    issue(0, 0);
    issue(1, BK);

    for (int kt = 0; kt < KT; ++kt) {
        cpa_wait1();
        __syncthreads();
        if (kt + 2 < KT) issue((kt + 2) % 3, (kt + 2) * BK);
        else cpa_commit();

        const int stage = kt % 3;
        const u32 ab = sbase + stage * STG;
        const u32 bb = ab + TSTG;
#pragma unroll
        for (int ks = 0; ks < 4; ++ks) {
            const int kk = ks * 16;
            u32 a[4][4], b[4][2];
#pragma unroll
            for (int mi = 0; mi < 4; ++mi)
                ldsm4(a[mi][0], a[mi][1], a[mi][2], a[mi][3],
                      ab + (u32)((rowA + mi * 16) * BKP + kk + colA) * 2);
#pragma unroll
            for (int p = 0; p < 2; ++p)
                ldsm4(b[2 * p][0], b[2 * p][1], b[2 * p + 1][0], b[2 * p + 1][1],
                      bb + (u32)((rowB + p * 16) * BKP + kk + colB) * 2);
#pragma unroll
            for (int mi = 0; mi < 4; ++mi)
#pragma unroll
                for (int nj = 0; nj < 4; ++nj)
                    hmma(acc[mi * 4 + nj], a[mi], b[nj]);
        }
    }
}

// ---------------- QKV projection (z selects Q/K/V; Q pre-scaled by QSCALE) ------
// z==2 (V) epilogue: smem transpose -> fully coalesced V^T writes.
__global__ void __launch_bounds__(256, 2)
qkv_proj(const __half* __restrict__ xh, const __half* __restrict__ wt,
         const float* __restrict__ b3, __half* __restrict__ qk,
         __half* __restrict__ vt, long QKoff)
{
    extern __shared__ __align__(16) __half smem[];
    const u32 sbase = (u32)__cvta_generic_to_shared(smem);
    const int z = blockIdx.z;
    const int m0 = blockIdx.y * 128, n0 = blockIdx.x * 128;

    const __half* Agp = xh + (long)m0 * DDIM;
    const __half* Bgp = wt + (long)z * DDIM * DDIM + (long)n0 * DDIM;
    const float* bias = b3 + z * DDIM;

    float acc[16][4];
    gemm_core_128(Agp, Bgp, DDIM, DDIM, DDIM, sbase, acc);

    const int tid = threadIdx.x;
    const int w = tid >> 5, lane = tid & 31;
    const int wm = w & 1, wn = w >> 1;
    const int gid = lane >> 2, tg = lane & 3;

    if (z < 2) {
        const float sc = (z == 0) ? QSCALE : 1.f;
        __half* Ch = qk + z * QKoff;
#pragma unroll
        for (int mi = 0; mi < 4; ++mi) {
            int r = m0 + wm * 64 + mi * 16 + gid;
#pragma unroll
            for (int nj = 0; nj < 4; ++nj) {
                int n = n0 + wn * 32 + nj * 8 + 2 * tg;
                float b0 = bias[n], b1 = bias[n + 1];
                float* c = acc[mi * 4 + nj];
                *(u32*)&Ch[(long)r * DDIM + n]       = pkh2((c[0] + b0) * sc, (c[1] + b1) * sc);
                *(u32*)&Ch[(long)(r + 8) * DDIM + n] = pkh2((c[2] + b0) * sc, (c[3] + b1) * sc);
            }
        }
    } else {
        // ---- V: transpose through smem, then coalesced global writes ----------
        __syncthreads();                       // stage smem now dead everywhere
        __half* T = smem;                      // [128 n][136 halves] padded tile
#pragma unroll
        for (int mi = 0; mi < 4; ++mi) {
            int rl = wm * 64 + mi * 16 + gid;
#pragma unroll
            for (int nj = 0; nj < 4; ++nj) {
                int nl = wn * 32 + nj * 8 + 2 * tg;
                float b0 = bias[n0 + nl], b1 = bias[n0 + nl + 1];
                float* c = acc[mi * 4 + nj];
                T[nl * 136 + rl]           = __float2half(c[0] + b0);
                T[(nl + 1) * 136 + rl]     = __float2half(c[1] + b1);
                T[nl * 136 + rl + 8]       = __float2half(c[2] + b0);
                T[(nl + 1) * 136 + rl + 8] = __float2half(c[3] + b1);
            }
        }
        __syncthreads();

        const int bb = m0 >> 11, s0 = m0 & 2047;
        __half* Vb = vt + ((long)(bb * NHEAD) * HDIM) * SLEN + s0;
#pragma unroll
        for (int i = 0; i < 8; ++i) {
            int idx = tid + i * 256;
            int n = idx >> 4, c = idx & 15;           // 16 uint4 per n-row
            uint4 v = *(const uint4*)&T[n * 136 + c * 8];
            *(uint4*)&Vb[(long)(n0 + n) * SLEN + c * 8] = v;
        }
    }
}

// ---------------- merged out-projection + region-major attn_mean -----------------
__global__ void __launch_bounds__(256, 2)
outmerge(const __half* __restrict__ ctx, const __half* __restrict__ wo,
         const float* __restrict__ bo, float* __restrict__ out,
         const __half* __restrict__ E, const float* __restrict__ rs,
         float* __restrict__ attn)
{
    const int bid = blockIdx.x;
    const int tid = threadIdx.x;

    if (bid < 256) {
        extern __shared__ __align__(16) __half smem[];
        const u32 sbase = (u32)__cvta_generic_to_shared(smem);
        const int m0 = (bid >> 3) * 128, n0 = (bid & 7) * 128;
        const __half* Agp = ctx + (long)m0 * DDIM;
        const __half* Bgp = wo + (long)n0 * DDIM;

        float acc[16][4];
        gemm_core_128(Agp, Bgp, DDIM, DDIM, DDIM, sbase, acc);

        const int w = tid >> 5, lane = tid & 31;
        const int wm = w & 1, wn = w >> 1;
        const int gid = lane >> 2, tg = lane & 3;
#pragma unroll
        for (int mi = 0; mi < 4; ++mi) {
            int r = m0 + wm * 64 + mi * 16 + gid;
#pragma unroll
            for (int nj = 0; nj < 4; ++nj) {
                int n = n0 + wn * 32 + nj * 8 + 2 * tg;
                float b0 = bo[n], b1 = bo[n + 1];
                float* c = acc[mi * 4 + nj];
                *(float2*)&out[(long)r * DDIM + n]       = make_float2(c[0] + b0, c[1] + b1);
                *(float2*)&out[(long)(r + 8) * DDIM + n] = make_float2(c[2] + b0, c[3] + b1);
            }
        }
    } else {
        const int id = bid - 256;
        const int kt = id & 15;
        const int rowblk = (id >> 4) & 63;
        const int b = id >> 10;

        __shared__ float siz2[NHEAD][32];
        for (int i = tid; i < NHEAD * 32; i += 256) {
            int hh2 = i >> 5, r = i & 31;
            siz2[hh2][r] = rs[(long)(b * NHEAD + hh2) * SLEN + rowblk * 32 + r];
        }
        __syncthreads();

        const int ch = tid >> 3, gid = tid & 7;
        const int mi = (ch >> 4) & 1, hhb = (ch >> 3) & 1, nj = (ch >> 1) & 3, p8 = ch & 1;
        const int row = mi * 16 + p8 * 8 + gid;
        const int colb = hhb * 32 + nj * 8;

        const u32* Eu = (const u32*)E;
        const long regbase0 = ((((long)(b * NHEAD) * 64 + rowblk) * 16 + kt) * 2);

        float a0[8] = {0,0,0,0,0,0,0,0};
        float a1[8] = {0,0,0,0,0,0,0,0};
#pragma unroll
        for (int h = 0; h < NHEAD; ++h) {
            float z = siz2[h][row];
            const u32* rg = Eu + (regbase0 + (long)h * (64 * 16 * 2)) * 1024 + tid * 4;
            uint4 e0 = *(const uint4*)rg;
            uint4 e1 = *(const uint4*)(rg + 1024);
            float2 f;
            f = __half22float2(*(__half2*)&e0.x); a0[0] += f.x * z; a0[1] += f.y * z;
            f = __half22float2(*(__half2*)&e0.y); a0[2] += f.x * z; a0[3] += f.y * z;
            f = __half22float2(*(__half2*)&e0.z); a0[4] += f.x * z; a0[5] += f.y * z;
            f = __half22float2(*(__half2*)&e0.w); a0[6] += f.x * z; a0[7] += f.y * z;
            f = __half22float2(*(__half2*)&e1.x); a1[0] += f.x * z; a1[1] += f.y * z;
            f = __half22float2(*(__half2*)&e1.y); a1[2] += f.x * z; a1[3] += f.y * z;
            f = __half22float2(*(__half2*)&e1.z); a1[4] += f.x * z; a1[5] += f.y * z;
            f = __half22float2(*(__half2*)&e1.w); a1[6] += f.x * z; a1[7] += f.y * z;
        }
        const float sc = 1.f / (float)NHEAD;
        float* o = attn + ((long)b * SLEN + rowblk * 32 + row) * SLEN + kt * 128 + colb;
        *(float4*)&o[0]  = make_float4(a0[0] * sc, a0[1] * sc, a0[2] * sc, a0[3] * sc);
        *(float4*)&o[4]  = make_float4(a0[4] * sc, a0[5] * sc, a0[6] * sc, a0[7] * sc);
        *(float4*)&o[64] = make_float4(a1[0] * sc, a1[1] * sc, a1[2] * sc, a1[3] * sc);
        *(float4*)&o[68] = make_float4(a1[4] * sc, a1[5] * sc, a1[6] * sc, a1[7] * sc);
    }
}

// ---------------- fused attention (R14 verbatim: tensor-core Z, permuted E) ------
__global__ void __launch_bounds__(128, 2)
fused_attn(const __half* __restrict__ Q, const __half* __restrict__ Kg,
           const __half* __restrict__ Vt, __half* __restrict__ E,
           __half* __restrict__ ctx, float* __restrict__ rs)
{
    constexpr int QP = 72;
    constexpr int VP = 136;
    constexpr int KTILE = 128 * QP;
    constexpr int VTILE = 64 * VP;
    constexpr int STAGE = KTILE + VTILE;
    constexpr int NC = SLEN / 128;

    const int tid = threadIdx.x;
    const int m0 = blockIdx.x * 64;
    const int bh = blockIdx.y;
    const int b = bh / NHEAD, h = bh % NHEAD;

    const __half* Qg = Q  + ((long)b * SLEN + m0) * DDIM + h * HDIM;
    const __half* Kb = Kg + ((long)b * SLEN) * DDIM + h * HDIM;
    const __half* Vg = Vt + (long)bh * HDIM * SLEN;

    const int w = tid >> 5, lane = tid & 31;
    const int gid = lane >> 2, tg = lane & 3;
    const int wm = w & 1, wn = w >> 1;
    const int q8 = lane >> 3, r8 = lane & 7;
    const int rowA = wm * 32 + (q8 & 1) * 8 + r8, colA = (q8 >> 1) * 8;
    const int rowB = wn * 64 + (q8 >> 1) * 8 + r8, colB = (q8 & 1) * 8;
    const int rowV = (q8 >> 1) * 8 + r8,            colV = (q8 & 1) * 8;

    u32* Eu = (u32*)E;
    const long rb16 = ((long)bh * 64 + blockIdx.x * 2 + wm) * 16;

    const u32 bzc = (gid == 0) ? 0x3C003C00u : 0u;
    const u32 bz[2] = { bzc, bzc };

    extern __shared__ __align__(16) __half smem[];
    const u32 sbase = (u32)__cvta_generic_to_shared(smem);
    auto kb = [&](int s) { return sbase + (u32)(s * STAGE) * 2; };
    auto vb = [&](int s) { return sbase + (u32)(s * STAGE + KTILE) * 2; };
    const u32 qb = kb(2);

    __shared__ float zs[2][32][2];
    __shared__ float siz[64];

    auto load_q = [&]() {
#pragma unroll
        for (int i = 0; i < 4; ++i) {
            int c = tid + i * 128; int row = c >> 3, cq = c & 7;
            cpa16(qb + (row * QP + cq * 8) * 2, Qg + (long)row * DDIM + cq * 8);
        }
    };
    auto issue = [&](int chunk) {
        const int stage = chunk % 3;
        const __half* Kp = Kb + (long)(chunk * 128) * DDIM;
        const u32 kbs = kb(stage);
#pragma unroll
        for (int i = 0; i < 8; ++i) {
            int c = tid + i * 128; int row = c >> 3, cq = c & 7;
            cpa16(kbs + (row * QP + cq * 8) * 2, Kp + (long)row * DDIM + cq * 8);
        }
        const __half* Vp = Vg + chunk * 128;
        const u32 vbs = vb(stage);
#pragma unroll
        for (int i = 0; i < 8; ++i) {
            int c = tid + i * 128; int row = c >> 4, cv = c & 15;
            cpa16(vbs + (row * VP + cv * 8) * 2, Vp + (long)row * SLEN + cv * 8);
        }
        cpa_commit();
    };

    float cU[2][8][4];
#pragma unroll
    for (int mi = 0; mi < 2; ++mi)
#pragma unroll
        for (int dj = 0; dj < 8; ++dj)
#pragma unroll
            for (int r = 0; r < 4; ++r) cU[mi][dj][r] = 0.f;
    float cUz[2][4];
#pragma unroll
    for (int mi = 0; mi < 2; ++mi)
#pragma unroll
        for (int r = 0; r < 4; ++r) cUz[mi][r] = 0.f;

    u32 qf[2][4][4];

    load_q();
    issue(0);
    issue(1);

    for (int kt = 0; kt < NC; ++kt) {
        cpa_wait1();
        __syncthreads();

        if (kt == 0) {
#pragma unroll
            for (int mi = 0; mi < 2; ++mi)
#pragma unroll
                for (int kf = 0; kf < 4; ++kf)
                    ldsm4(qf[mi][kf][0], qf[mi][kf][1], qf[mi][kf][2], qf[mi][kf][3],
                          qb + ((rowA + mi * 16) * QP + kf * 16 + colA) * 2);
            __syncthreads();
        }

        if (kt + 2 < NC) issue(kt + 2);
        else cpa_commit();

        const int stage = kt % 3;
        const u32 kbs = kb(stage), vbs = vb(stage);
        u32* Ew = Eu + ((rb16 + kt) * 2 + wn) * 1024 + lane;

#pragma unroll
        for (int hh = 0; hh < 2; ++hh) {
            float cS[2][4][4];
#pragma unroll
            for (int mi = 0; mi < 2; ++mi)
#pragma unroll
                for (int nj = 0; nj < 4; ++nj)
#pragma unroll
                    for (int r = 0; r < 4; ++r) cS[mi][nj][r] = 0.f;

#pragma unroll
            for (int kf = 0; kf < 4; ++kf) {
                const int kk = kf * 16;
                u32 bfr[4][2];
#pragma unroll
                for (int p = 0; p < 2; ++p) {
                    const int pg = 2 * hh + p;
                    ldsm4(bfr[2 * p][0], bfr[2 * p][1], bfr[2 * p + 1][0], bfr[2 * p + 1][1],
                          kbs + ((rowB + pg * 16) * QP + kk + colB) * 2);
                }
#pragma unroll
                for (int mi = 0; mi < 2; ++mi)
#pragma unroll
                    for (int nj = 0; nj < 4; ++nj)
                        hmma(cS[mi][nj], qf[mi][kf], bfr[nj]);
            }

            u32 eh[2][4][2];
#pragma unroll
            for (int mi = 0; mi < 2; ++mi)
#pragma unroll
                for (int nj = 0; nj < 4; ++nj) {
                    eh[mi][nj][0] = ex2h2(pkh2(cS[mi][nj][0], cS[mi][nj][1]));
                    eh[mi][nj][1] = ex2h2(pkh2(cS[mi][nj][2], cS[mi][nj][3]));
                }

#pragma unroll
            for (int j = 0; j < 2; ++j) {
                const int kfu = 2 * hh + j;
                const int kk2 = kfu * 16;
                u32 a[2][4], bv[8][2];
#pragma unroll
                for (int mi = 0; mi < 2; ++mi) {
                    a[mi][0] = eh[mi][2 * j][0];
                    a[mi][1] = eh[mi][2 * j][1];
                    a[mi][2] = eh[mi][2 * j + 1][0];
                    a[mi][3] = eh[mi][2 * j + 1][1];
                }
#pragma unroll
                for (int p = 0; p < 4; ++p)
                    ldsm4(bv[2 * p][0], bv[2 * p][1], bv[2 * p + 1][0], bv[2 * p + 1][1],
                          vbs + ((rowV + p * 16) * VP + wn * 64 + kk2 + colV) * 2);
#pragma unroll
                for (int mi = 0; mi < 2; ++mi) {
#pragma unroll
                    for (int dj = 0; dj < 8; ++dj)
                        hmma(cU[mi][dj], a[mi], bv[dj]);
                    hmma(cUz[mi], a[mi], bz);
                }
            }

#pragma unroll
            for (int mi = 0; mi < 2; ++mi)
#pragma unroll
                for (int nj = 0; nj < 4; ++nj) {
                    const int ch = ((mi * 2 + hh) * 4 + nj) * 2;
                    Ew[(u32)(ch * 32)]       = eh[mi][nj][0];
                    Ew[(u32)((ch + 1) * 32)] = eh[mi][nj][1];
                }
        }
    }

    __syncthreads();

    if (tg == 0) {
#pragma unroll
        for (int mi = 0; mi < 2; ++mi) {
            zs[wm][mi * 16 + gid][wn]     = cUz[mi][0];
            zs[wm][mi * 16 + 8 + gid][wn] = cUz[mi][2];
        }
    }
    __syncthreads();
    if (tid < 64) {
        float inv = 1.f / (zs[tid >> 5][tid & 31][0] + zs[tid >> 5][tid & 31][1]);
        siz[tid] = inv;
        rs[(long)bh * SLEN + m0 + tid] = inv;
    }
    __syncthreads();

    float* Ured = (float*)smem;
    if (wn == 1) {
#pragma unroll
        for (int mi = 0; mi < 2; ++mi) {
            int r = wm * 32 + mi * 16 + gid;
#pragma unroll
            for (int dj = 0; dj < 8; ++dj) {
                int n = dj * 8 + 2 * tg;
                *(float2*)&Ured[r * 68 + n]       = make_float2(cU[mi][dj][0], cU[mi][dj][1]);
                *(float2*)&Ured[(r + 8) * 68 + n] = make_float2(cU[mi][dj][2], cU[mi][dj][3]);
            }
        }
    }
    __syncthreads();
    if (wn == 0) {
#pragma unroll
        for (int mi = 0; mi < 2; ++mi) {
            int r = wm * 32 + mi * 16 + gid;
            float iz0 = siz[r], iz1 = siz[r + 8];
            __half* C0 = ctx + ((long)b * SLEN + m0 + r) * DDIM + h * HDIM;
#pragma unroll
            for (int dj = 0; dj < 8; ++dj) {
                int n = dj * 8 + 2 * tg;
                float2 u0 = *(const float2*)&Ured[r * 68 + n];
                float2 u1 = *(const float2*)&Ured[(r + 8) * 68 + n];
                *(u32*)&C0[n] = pkh2((cU[mi][dj][0] + u0.x) * iz0,
                                     (cU[mi][dj][1] + u0.y) * iz0);
                *(u32*)&C0[8L * DDIM + n] = pkh2((cU[mi][dj][2] + u1.x) * iz1,
                                                 (cU[mi][dj][3] + u1.y) * iz1);
            }
        }
    }
}

// ---------------- prep kernels ----------------------------------------------------
__global__ void __launch_bounds__(256)
prep_w(const float* __restrict__ W0, const float* __restrict__ W1,
       const float* __restrict__ W2, const float* __restrict__ W3,
       __half* __restrict__ Wt)
{
    const int z = blockIdx.z;
    const float* W = (z == 0) ? W0 : (z == 1) ? W1 : (z == 2) ? W2 : W3;
    __half* T = Wt + (long)z * DDIM * DDIM;
    __shared__ float t[32][33];
    const int tx = threadIdx.x, ty = threadIdx.y;
    const int n0 = blockIdx.x * 32, k0 = blockIdx.y * 32;
#pragma unroll
    for (int i = 0; i < 4; ++i)
        t[tx][ty + 8 * i] = W[(long)(k0 + ty + 8 * i) * DDIM + n0 + tx];
    __syncthreads();
#pragma unroll
    for (int i = 0; i < 4; ++i)
        T[(long)(n0 + ty + 8 * i) * DDIM + k0 + tx] = __float2half(t[ty + 8 * i][tx]);
}

__global__ void __launch_bounds__(256)
prep_x(const float* __restrict__ x, __half* __restrict__ xh)
{
    long i = ((long)blockIdx.x * 256 + threadIdx.x) * 8;
    float4 f0 = *(const float4*)(x + i);
    float4 f1 = *(const float4*)(x + i + 4);
    uint4 u;
    u.x = pkh2(f0.x, f0.y); u.y = pkh2(f0.z, f0.w);
    u.z = pkh2(f1.x, f1.y); u.w = pkh2(f1.z, f1.w);
    *(uint4*)(xh + i) = u;
}

// ---------------- launch -----------------------------------------------------------
extern "C" void kernel_launch(void* const* d_in, const int* in_sizes, int n_in,
                              void* d_out, int out_size)
{
    const float* x  = (const float*)d_in[0];
    const float* Wq = (const float*)d_in[1];
    const float* bq = (const float*)d_in[2];
    const float* Wk = (const float*)d_in[3];
    const float* bk = (const float*)d_in[4];
    const float* Wv = (const float*)d_in[5];
    const float* bv = (const float*)d_in[6];
    const float* Wo = (const float*)d_in[7];
    const float* bo = (const float*)d_in[8];
    float* out = (float*)d_out;

    const int Bsz = in_sizes[0] / (SLEN * DDIM);   // = 2
    const int BS  = Bsz * SLEN;
    const long NB = (long)BS * DDIM;

    __half *wt, *xh, *qk, *vt, *E, *ctx;
    float *b3, *rs;
    cudaGetSymbolAddress((void**)&wt,  g_wt);
    cudaGetSymbolAddress((void**)&b3,  g_b3);
    cudaGetSymbolAddress((void**)&xh,  g_xh);
    cudaGetSymbolAddress((void**)&qk,  g_qk);
    cudaGetSymbolAddress((void**)&vt,  g_vt);
    cudaGetSymbolAddress((void**)&E,   g_E);
    cudaGetSymbolAddress((void**)&ctx, g_ctx);
    cudaGetSymbolAddress((void**)&rs,  g_rs);

    const int SM_P = 3 * 2 * 128 * 72 * 2;                 // 110592 (gemm core)
    const int SM_F = 3 * (128 * 72 + 64 * 136) * 2;        // 107520 (fused)
    cudaFuncSetAttribute(qkv_proj,   cudaFuncAttributeMaxDynamicSharedMemorySize, SM_P);
    cudaFuncSetAttribute(outmerge,   cudaFuncAttributeMaxDynamicSharedMemorySize, SM_P);
    cudaFuncSetAttribute(fused_attn, cudaFuncAttributeMaxDynamicSharedMemorySize, SM_F);

    cudaMemcpyAsync(b3,            bq, sizeof(float) * DDIM, cudaMemcpyDeviceToDevice);
    cudaMemcpyAsync(b3 + DDIM,     bk, sizeof(float) * DDIM, cudaMemcpyDeviceToDevice);
    cudaMemcpyAsync(b3 + 2 * DDIM, bv, sizeof(float) * DDIM, cudaMemcpyDeviceToDevice);

    prep_x<<<(unsigned)(NB / (256 * 8)), 256>>>(x, xh);
    prep_w<<<dim3(32, 32, 4), dim3(32, 8)>>>(Wq, Wk, Wv, Wo, wt);

    const long QKoff = (long)BS * DDIM;

    qkv_proj<<<dim3(8, BS / 128, 3), 256, SM_P>>>(xh, wt, b3, qk, vt, QKoff);

    fused_attn<<<dim3(SLEN / 64, Bsz * NHEAD), 128, SM_F>>>(
        qk, qk + QKoff, vt, E, ctx, rs);

    outmerge<<<256 + Bsz * 1024, 256, SM_P>>>(
        ctx, wt + 3L * DDIM * DDIM, bo, out, E, rs, out + NB);
}